// round 12
// baseline (speedup 1.0000x reference)
#include <cuda_runtime.h>

// 2-layer LSTM (H=51), B=512, T=512, scalar in, linear head, future=0.
// 128 persistent blocks, BB=4 rows, 672 threads (21 warps ~ 5/SMSP).
// 3-stage pipeline (R11 protocol): G1=Whh1+combine, G2=Wih2->zring, G3=Whh2+combine.
// Thread = 1 gate x 4 batches x FULL K: w in regs (26 f32x2), broadcast LDS,
// no k-reduce; gate gathering via in-quad 4x4 shuffle transpose; 1 cell/thread.

#define H    51
#define HP   56
#define BHP  (4*HP)
#define TT   512
#define NTH  672
#define NBLK 128
#define NIT  513
#define ZS   816

#define BF1 1
#define BE1 2
#define BFZ 3
#define BEZ 4
#define BCNT 448

typedef unsigned long long ull;

__device__ __forceinline__ void bar_sync_n(int id) {
    asm volatile("bar.sync %0, %1;" :: "r"(id), "r"(BCNT) : "memory");
}
__device__ __forceinline__ void bar_arrive_n(int id) {
    asm volatile("bar.arrive %0, %1;" :: "r"(id), "r"(BCNT) : "memory");
}
__device__ __forceinline__ ull fma2(ull a, ull b, ull c) {
    ull d; asm("fma.rn.f32x2 %0, %1, %2, %3;" : "=l"(d) : "l"(a), "l"(b), "l"(c)); return d;
}
__device__ __forceinline__ ull add2(ull a, ull b) {
    ull d; asm("add.rn.f32x2 %0, %1, %2;" : "=l"(d) : "l"(a), "l"(b)); return d;
}
__device__ __forceinline__ ull pack2(float lo, float hi) {
    ull d; asm("mov.b64 %0, {%1, %2};" : "=l"(d) : "f"(lo), "f"(hi)); return d;
}
__device__ __forceinline__ float sum2(ull a) {
    float x, y; asm("mov.b64 {%0, %1}, %2;" : "=f"(x), "=f"(y) : "l"(a)); return x + y;
}
__device__ __forceinline__ float tanhap(float x) {
    float y; asm("tanh.approx.f32 %0, %1;" : "=f"(y) : "f"(x)); return y;
}
__device__ __forceinline__ float sigap(float x) {
    return fmaf(0.5f, tanhap(0.5f * x), 0.5f);
}

// in-quad 4x4 transpose: lane q of each quad ends with element q of all 4 lanes
__device__ __forceinline__ void quad_transpose(float z[4], int q, unsigned qmask) {
    {   // phase A: xor 1 on elements with bit0 != (q&1)
        float t0 = __shfl_xor_sync(qmask, (q & 1) ? z[0] : z[1], 1);
        float t1 = __shfl_xor_sync(qmask, (q & 1) ? z[2] : z[3], 1);
        if (q & 1) { z[0] = t0; z[2] = t1; } else { z[1] = t0; z[3] = t1; }
    }
    {   // phase B: xor 2 on elements with bit1 != (q&2)
        float t0 = __shfl_xor_sync(qmask, (q & 2) ? z[0] : z[2], 2);
        float t1 = __shfl_xor_sync(qmask, (q & 2) ? z[1] : z[3], 2);
        if (q & 2) { z[0] = t0; z[1] = t1; } else { z[2] = t0; z[3] = t1; }
    }
}

__global__ __launch_bounds__(NTH, 1)
void lstm2_kernel(const float* __restrict__ input,
                  const float* __restrict__ W_ih1,
                  const float* __restrict__ W_hh1,
                  const float* __restrict__ b_ih1,
                  const float* __restrict__ b_hh1,
                  const float* __restrict__ W_ih2,
                  const float* __restrict__ W_hh2,
                  const float* __restrict__ b_ih2,
                  const float* __restrict__ b_hh2,
                  const float* __restrict__ W_lin,
                  const float* __restrict__ b_lin,
                  float* __restrict__ out)
{
    __shared__ __align__(16) float hbuf[2*BHP + 8 + 2*BHP];
    __shared__ __align__(16) float zring[2*ZS];
    __shared__ float xall[4*TT];
    __shared__ float wlins[56];

    float* const h1b = hbuf;
    float* const h2b = hbuf + 2*BHP + 8;

    const int tid  = threadIdx.x;
    const int lane = tid & 31;
    const int wid  = tid >> 5;
    const int row0 = blockIdx.x * 4;

    const int grp  = (tid < 224) ? 0 : ((tid < 448) ? 1 : 2);
    const int l    = tid - grp*224;       // 0..223 within stage
    const bool act = (l < 204);
    const int u    = l >> 2;              // hidden unit 0..50
    const int q    = l & 3;               // gate index (matmul) / batch (post-transpose)
    const bool isOut = (wid == 20) && (lane >= 16 && lane < 24);

    const unsigned qmask = 0xFu << (lane & 28);
    const unsigned pmask = 0x3u << (lane & 30);

    // ---- init smem ----
    for (int i = tid; i < 2*BHP + 8 + 2*BHP; i += NTH) hbuf[i] = 0.0f;
    for (int i = tid; i < 2*ZS; i += NTH) zring[i] = 0.0f;
    for (int i = tid; i < 4*TT; i += NTH) {
        const int b = i >> 9;
        const int t = i & (TT - 1);
        xall[i] = input[(row0 + b)*TT + t];
    }
    for (int i = tid; i < 56; i += NTH) wlins[i] = (i < H) ? W_lin[i] : 0.0f;

    // ---- one full weight row -> 26 f32x2 regs ----
    ull w2[26];
    float bz = 0.f, wx = 0.f;
    if (act) {
        const float* W = (grp == 0) ? W_hh1 : ((grp == 1) ? W_ih2 : W_hh2);
        const int r = u + 51*q;
        #pragma unroll
        for (int m = 0; m < 25; ++m)
            w2[m] = pack2(W[r*H + 2*m], W[r*H + 2*m + 1]);
        w2[25] = pack2(W[r*H + 50], 0.0f);
        if (grp == 0) { bz = b_ih1[r] + b_hh1[r]; wx = W_ih1[r]; }
        if (grp == 2) { bz = b_ih2[r] + b_hh2[r]; }
    }

    float blin = 0.0f; int ob = 0, half = 0;
    if (isOut) {
        const int o = lane - 16;
        ob = o >> 1; half = o & 1;
        blin = b_lin[0];
    }

    float cst = 0.f;
    __syncthreads();

    if (grp == 0) {
        // =============== G1: layer-1 recurrence ===============
        for (int t = 0; t < NIT; ++t) {
            const int sl = t & 1;
            bar_sync_n(sl ? (BE1 + 4) : BE1);
            if (act && t < TT) {
                const float* hb = h1b + (sl^1)*BHP;   // h1(t-1)
                ull ax0=0ull, ax1=0ull, ax2=0ull, ax3=0ull;
                ull ay0=0ull, ay1=0ull, ay2=0ull, ay3=0ull;
                #pragma unroll
                for (int j = 0; j < 13; ++j) {
                    const ull w0 = w2[2*j], w1 = w2[2*j+1];
                    const ulonglong2 u0 = *reinterpret_cast<const ulonglong2*>(hb + 0*HP + 4*j);
                    const ulonglong2 u1 = *reinterpret_cast<const ulonglong2*>(hb + 1*HP + 4*j);
                    const ulonglong2 u2 = *reinterpret_cast<const ulonglong2*>(hb + 2*HP + 4*j);
                    const ulonglong2 u3 = *reinterpret_cast<const ulonglong2*>(hb + 3*HP + 4*j);
                    ax0 = fma2(w0, u0.x, ax0);  ay0 = fma2(w1, u0.y, ay0);
                    ax1 = fma2(w0, u1.x, ax1);  ay1 = fma2(w1, u1.y, ay1);
                    ax2 = fma2(w0, u2.x, ax2);  ay2 = fma2(w1, u2.y, ay2);
                    ax3 = fma2(w0, u3.x, ax3);  ay3 = fma2(w1, u3.y, ay3);
                }
                float z[4];
                z[0] = sum2(add2(ax0, ay0));
                z[1] = sum2(add2(ax1, ay1));
                z[2] = sum2(add2(ax2, ay2));
                z[3] = sum2(add2(ax3, ay3));
                #pragma unroll
                for (int b = 0; b < 4; ++b)
                    z[b] = fmaf(xall[b*TT + t], wx, z[b] + bz);
                quad_transpose(z, q, qmask);           // now z = 4 gates for batch q
                const float ig = sigap(z[0]), fg = sigap(z[1]);
                const float gg = tanhap(z[2]), og = sigap(z[3]);
                cst = fmaf(fg, cst, ig*gg);
                h1b[sl*BHP + q*HP + u] = og * tanhap(cst);
            }
            bar_arrive_n(sl ? (BF1 + 4) : BF1);
        }
    } else if (grp == 1) {
        // =============== G2: Wih2 * h1(t) -> z-ring ===============
        bar_arrive_n(BE1);
        bar_arrive_n(BE1 + 4);
        for (int t = 0; t < NIT; ++t) {
            const int sl = t & 1;
            bar_sync_n(sl ? (BF1 + 4) : BF1);
            bar_sync_n(sl ? (BEZ + 4) : BEZ);
            if (act && t < TT) {
                const float* hb = h1b + sl*BHP;       // h1(t)
                ull ax0=0ull, ax1=0ull, ax2=0ull, ax3=0ull;
                ull ay0=0ull, ay1=0ull, ay2=0ull, ay3=0ull;
                #pragma unroll
                for (int j = 0; j < 13; ++j) {
                    const ull w0 = w2[2*j], w1 = w2[2*j+1];
                    const ulonglong2 u0 = *reinterpret_cast<const ulonglong2*>(hb + 0*HP + 4*j);
                    const ulonglong2 u1 = *reinterpret_cast<const ulonglong2*>(hb + 1*HP + 4*j);
                    const ulonglong2 u2 = *reinterpret_cast<const ulonglong2*>(hb + 2*HP + 4*j);
                    const ulonglong2 u3 = *reinterpret_cast<const ulonglong2*>(hb + 3*HP + 4*j);
                    ax0 = fma2(w0, u0.x, ax0);  ay0 = fma2(w1, u0.y, ay0);
                    ax1 = fma2(w0, u1.x, ax1);  ay1 = fma2(w1, u1.y, ay1);
                    ax2 = fma2(w0, u2.x, ax2);  ay2 = fma2(w1, u2.y, ay2);
                    ax3 = fma2(w0, u3.x, ax3);  ay3 = fma2(w1, u3.y, ay3);
                }
                float4 zv;
                zv.x = sum2(add2(ax0, ay0));
                zv.y = sum2(add2(ax1, ay1));
                zv.z = sum2(add2(ax2, ay2));
                zv.w = sum2(add2(ax3, ay3));
                *reinterpret_cast<float4*>(zring + sl*ZS + 4*l) = zv;
            }
            bar_arrive_n(sl ? (BFZ + 4) : BFZ);
            bar_arrive_n(sl ? (BE1 + 4) : BE1);
        }
    } else {
        // =============== G3: Whh2 + combine; out-head ===============
        bar_arrive_n(BEZ);
        bar_arrive_n(BEZ + 4);
        for (int t = 0; t < NIT; ++t) {
            const int sl = t & 1;
            bar_sync_n(sl ? (BFZ + 4) : BFZ);
            if (act && t < TT) {
                const float* hb = h2b + (sl^1)*BHP;   // h2(t-1)
                ull ax0=0ull, ax1=0ull, ax2=0ull, ax3=0ull;
                ull ay0=0ull, ay1=0ull, ay2=0ull, ay3=0ull;
                #pragma unroll
                for (int j = 0; j < 13; ++j) {
                    const ull w0 = w2[2*j], w1 = w2[2*j+1];
                    const ulonglong2 u0 = *reinterpret_cast<const ulonglong2*>(hb + 0*HP + 4*j);
                    const ulonglong2 u1 = *reinterpret_cast<const ulonglong2*>(hb + 1*HP + 4*j);
                    const ulonglong2 u2 = *reinterpret_cast<const ulonglong2*>(hb + 2*HP + 4*j);
                    const ulonglong2 u3 = *reinterpret_cast<const ulonglong2*>(hb + 3*HP + 4*j);
                    ax0 = fma2(w0, u0.x, ax0);  ay0 = fma2(w1, u0.y, ay0);
                    ax1 = fma2(w0, u1.x, ax1);  ay1 = fma2(w1, u1.y, ay1);
                    ax2 = fma2(w0, u2.x, ax2);  ay2 = fma2(w1, u2.y, ay2);
                    ax3 = fma2(w0, u3.x, ax3);  ay3 = fma2(w1, u3.y, ay3);
                }
                const float4 zp = *reinterpret_cast<const float4*>(zring + sl*ZS + 4*l);
                float z[4];
                z[0] = sum2(add2(ax0, ay0)) + zp.x + bz;
                z[1] = sum2(add2(ax1, ay1)) + zp.y + bz;
                z[2] = sum2(add2(ax2, ay2)) + zp.z + bz;
                z[3] = sum2(add2(ax3, ay3)) + zp.w + bz;
                quad_transpose(z, q, qmask);           // now z = 4 gates for batch q
                const float ig = sigap(z[0]), fg = sigap(z[1]);
                const float gg = tanhap(z[2]), og = sigap(z[3]);
                cst = fmaf(fg, cst, ig*gg);
                h2b[sl*BHP + q*HP + u] = og * tanhap(cst);
            }
            if (isOut && t >= 1) {
                const float* h2p = h2b + (sl^1)*BHP;  // h2(t-1)
                float v = 0.f;
                #pragma unroll
                for (int m = 0; m < 26; ++m)
                    v = fmaf(h2p[ob*HP + half*26 + m], wlins[half*26 + m], v);
                v += __shfl_xor_sync(pmask, v, 1);
                if (half == 0) out[(row0 + ob)*TT + (t - 1)] = v + blin;
            }
            bar_arrive_n(sl ? (BEZ + 4) : BEZ);
        }
    }
}

extern "C" void kernel_launch(void* const* d_in, const int* in_sizes, int n_in,
                              void* d_out, int out_size)
{
    const float* input = (const float*)d_in[0];
    const float* W_ih1 = (const float*)d_in[1];
    const float* W_hh1 = (const float*)d_in[2];
    const float* b_ih1 = (const float*)d_in[3];
    const float* b_hh1 = (const float*)d_in[4];
    const float* W_ih2 = (const float*)d_in[5];
    const float* W_hh2 = (const float*)d_in[6];
    const float* b_ih2 = (const float*)d_in[7];
    const float* b_hh2 = (const float*)d_in[8];
    const float* W_lin = (const float*)d_in[9];
    const float* b_lin = (const float*)d_in[10];
    float* out = (float*)d_out;

    lstm2_kernel<<<NBLK, NTH>>>(input, W_ih1, W_hh1, b_ih1, b_hh1,
                                W_ih2, W_hh2, b_ih2, b_hh2,
                                W_lin, b_lin, out);
}